// round 2
// baseline (speedup 1.0000x reference)
#include <cuda_runtime.h>
#include <math.h>

// ============================================================================
// AttentionHead: B=4, T=4096, E=1024, H=64, fp32, causal, scale = E^-0.5 = 1/32
// Round 1: fp32 SIMT baseline. Kernel 1: QKV projection SGEMM.
//          Kernel 2: flash-attention (online softmax), 64x64 tiles.
// ============================================================================

#define B_   4
#define T_   4096
#define E_   1024
#define H_   64
#define MROWS (B_ * T_)          // 16384

// scratch for q, k, v: [B*T][H] each
__device__ float g_q[MROWS * H_];
__device__ float g_k[MROWS * H_];
__device__ float g_v[MROWS * H_];

// ----------------------------------------------------------------------------
// Projection: C[m][n] = sum_e emb[m][e] * W[n][e]     (M=16384, N=64, K=1024)
// Tile: BM=128, BN=64, BK=16. 256 threads, 8x4 microtile per thread.
// grid.y in {0,1,2} selects Wq/Wk/Wv and output buffer.
// ----------------------------------------------------------------------------
#define BM 128
#define BN 64
#define BKP 16
#define AW_A (BM + 4)   // 132, multiple of 4 (float4-aligned rows)
#define AW_B (BN + 4)   // 68

__global__ __launch_bounds__(256) void proj_kernel(
    const float* __restrict__ emb,
    const float* __restrict__ Wq,
    const float* __restrict__ Wk,
    const float* __restrict__ Wv)
{
    __shared__ float As[BKP][AW_A];   // k-major: As[k][m]
    __shared__ float Bs[BKP][AW_B];   // k-major: Bs[k][n]

    const float* W = (blockIdx.y == 0) ? Wq : (blockIdx.y == 1) ? Wk : Wv;
    float* out     = (blockIdx.y == 0) ? g_q : (blockIdx.y == 1) ? g_k : g_v;

    const int tid = threadIdx.x;
    const int tx  = tid & 15;
    const int ty  = tid >> 4;
    const int row0 = blockIdx.x * BM;

    float acc[8][4];
    #pragma unroll
    for (int i = 0; i < 8; i++)
        #pragma unroll
        for (int j = 0; j < 4; j++) acc[i][j] = 0.0f;

    for (int k0 = 0; k0 < E_; k0 += BKP) {
        // Load A tile (128x16) transposed into As[k][m]: 512 float4, 2/thread
        #pragma unroll
        for (int it = 0; it < 2; it++) {
            int f  = tid + it * 256;
            int m  = f >> 2;         // 4 float4 per row (16 floats)
            int kv = f & 3;
            float4 v = *(const float4*)&emb[(size_t)(row0 + m) * E_ + k0 + kv * 4];
            As[kv * 4 + 0][m] = v.x;
            As[kv * 4 + 1][m] = v.y;
            As[kv * 4 + 2][m] = v.z;
            As[kv * 4 + 3][m] = v.w;
        }
        // Load B tile (64x16) transposed into Bs[k][n]: 256 float4, 1/thread
        {
            int n  = tid >> 2;
            int kv = tid & 3;
            float4 v = *(const float4*)&W[(size_t)n * E_ + k0 + kv * 4];
            Bs[kv * 4 + 0][n] = v.x;
            Bs[kv * 4 + 1][n] = v.y;
            Bs[kv * 4 + 2][n] = v.z;
            Bs[kv * 4 + 3][n] = v.w;
        }
        __syncthreads();

        #pragma unroll
        for (int kk = 0; kk < BKP; kk++) {
            float4 a0 = *(const float4*)&As[kk][ty * 8];
            float4 a1 = *(const float4*)&As[kk][ty * 8 + 4];
            float4 b0 = *(const float4*)&Bs[kk][tx * 4];
            float a[8] = {a0.x, a0.y, a0.z, a0.w, a1.x, a1.y, a1.z, a1.w};
            float bb[4] = {b0.x, b0.y, b0.z, b0.w};
            #pragma unroll
            for (int i = 0; i < 8; i++)
                #pragma unroll
                for (int j = 0; j < 4; j++)
                    acc[i][j] = fmaf(a[i], bb[j], acc[i][j]);
        }
        __syncthreads();
    }

    // Store: rows ty*8+i, cols tx*4..tx*4+3
    #pragma unroll
    for (int i = 0; i < 8; i++) {
        int m = row0 + ty * 8 + i;
        float4 v = make_float4(acc[i][0], acc[i][1], acc[i][2], acc[i][3]);
        *(float4*)&out[(size_t)m * H_ + tx * 4] = v;
    }
}

// ----------------------------------------------------------------------------
// Flash attention: per block, 64 queries of one batch; loop over causal key
// tiles of 64. 256 threads (16x16), 4x4 microtile.
// Smem (dynamic, 69632 B): Qt[64][68] (dim-major), Kt[64][68] (dim-major),
// Vs[64][68] (key-major), Pt[64][68] ([key][row]).
// ----------------------------------------------------------------------------
#define AW 68
#define NEG_INF (-1e30f)

__global__ __launch_bounds__(256) void attn_kernel(float* __restrict__ out)
{
    extern __shared__ float sm[];
    float (*Qt)[AW] = (float (*)[AW])(sm);                 // [dim][row]
    float (*Kt)[AW] = (float (*)[AW])(sm + 64 * AW);       // [dim][key]
    float (*Vs)[AW] = (float (*)[AW])(sm + 2 * 64 * AW);   // [key][dim]
    float (*Pt)[AW] = (float (*)[AW])(sm + 3 * 64 * AW);   // [key][row]

    const int tid = threadIdx.x;
    const int tx  = tid & 15;
    const int ty  = tid >> 4;
    const int b   = blockIdx.y;
    // Reverse so heaviest (most key tiles) blocks launch first
    const int qt  = gridDim.x - 1 - blockIdx.x;
    const int q0  = qt * 64;

    const float* qb = g_q + ((size_t)b * T_ + q0) * H_;
    const float* kb = g_k + (size_t)b * T_ * H_;
    const float* vb = g_v + (size_t)b * T_ * H_;

    // Load Q tile transposed: Qt[dim][row]
    #pragma unroll
    for (int it = 0; it < 4; it++) {
        int f  = tid + it * 256;
        int r  = f >> 4;        // 16 float4 per row
        int dv = f & 15;
        float4 v = *(const float4*)&qb[(size_t)r * H_ + dv * 4];
        Qt[dv * 4 + 0][r] = v.x;
        Qt[dv * 4 + 1][r] = v.y;
        Qt[dv * 4 + 2][r] = v.z;
        Qt[dv * 4 + 3][r] = v.w;
    }

    float m_[4], l_[4], O[4][4];
    #pragma unroll
    for (int i = 0; i < 4; i++) {
        m_[i] = NEG_INF;
        l_[i] = 0.0f;
        #pragma unroll
        for (int j = 0; j < 4; j++) O[i][j] = 0.0f;
    }

    const float scale = 0.03125f;  // E^-0.5 = 1/32
    const int ntiles = qt + 1;

    for (int t = 0; t < ntiles; t++) {
        const int k0 = t * 64;
        __syncthreads();  // prior GEMM1 (Kt) / GEMM2 (Vs, Pt) reads complete

        // Load K tile transposed + V tile natural
        #pragma unroll
        for (int it = 0; it < 4; it++) {
            int f  = tid + it * 256;
            int r  = f >> 4;
            int dv = f & 15;
            float4 v = *(const float4*)&kb[(size_t)(k0 + r) * H_ + dv * 4];
            Kt[dv * 4 + 0][r] = v.x;
            Kt[dv * 4 + 1][r] = v.y;
            Kt[dv * 4 + 2][r] = v.z;
            Kt[dv * 4 + 3][r] = v.w;
            float4 w = *(const float4*)&vb[(size_t)(k0 + r) * H_ + dv * 4];
            *(float4*)&Vs[r][dv * 4] = w;
        }
        __syncthreads();

        // GEMM1: S[r][c] = sum_d Q[r][d] * K[c][d]
        float S[4][4];
        #pragma unroll
        for (int i = 0; i < 4; i++)
            #pragma unroll
            for (int j = 0; j < 4; j++) S[i][j] = 0.0f;

        #pragma unroll 16
        for (int kk = 0; kk < 64; kk++) {
            float4 a  = *(const float4*)&Qt[kk][ty * 4];
            float4 b4 = *(const float4*)&Kt[kk][tx * 4];
            float av[4] = {a.x, a.y, a.z, a.w};
            float bv[4] = {b4.x, b4.y, b4.z, b4.w};
            #pragma unroll
            for (int i = 0; i < 4; i++)
                #pragma unroll
                for (int j = 0; j < 4; j++)
                    S[i][j] = fmaf(av[i], bv[j], S[i][j]);
        }

        // Scale, causal mask, online softmax update
        #pragma unroll
        for (int i = 0; i < 4; i++) {
            const int qg = q0 + ty * 4 + i;
            float mx = NEG_INF;
            #pragma unroll
            for (int j = 0; j < 4; j++) {
                const int kg = k0 + tx * 4 + j;
                float s = (kg <= qg) ? S[i][j] * scale : NEG_INF;
                S[i][j] = s;
                mx = fmaxf(mx, s);
            }
            // reduce max over the 16 tx lanes (lane bits 0..3)
            #pragma unroll
            for (int d = 1; d < 16; d <<= 1)
                mx = fmaxf(mx, __shfl_xor_sync(0xffffffffu, mx, d));
            const float mnew = fmaxf(m_[i], mx);
            const float al = __expf(m_[i] - mnew);
            float rs = 0.0f;
            #pragma unroll
            for (int j = 0; j < 4; j++) {
                float p = __expf(S[i][j] - mnew);
                S[i][j] = p;
                rs += p;
            }
            #pragma unroll
            for (int d = 1; d < 16; d <<= 1)
                rs += __shfl_xor_sync(0xffffffffu, rs, d);
            l_[i] = l_[i] * al + rs;
            m_[i] = mnew;
            #pragma unroll
            for (int j = 0; j < 4; j++) O[i][j] *= al;
        }

        // Store P transposed: Pt[key][row]
        #pragma unroll
        for (int i = 0; i < 4; i++)
            #pragma unroll
            for (int j = 0; j < 4; j++)
                Pt[tx * 4 + j][ty * 4 + i] = S[i][j];
        __syncthreads();

        // GEMM2: O[r][d] += sum_k P[r][k] * V[k][d]
        #pragma unroll 16
        for (int kk = 0; kk < 64; kk++) {
            float4 a  = *(const float4*)&Pt[kk][ty * 4];
            float4 v4 = *(const float4*)&Vs[kk][tx * 4];
            float av[4] = {a.x, a.y, a.z, a.w};
            float vv[4] = {v4.x, v4.y, v4.z, v4.w};
            #pragma unroll
            for (int i = 0; i < 4; i++)
                #pragma unroll
                for (int j = 0; j < 4; j++)
                    O[i][j] = fmaf(av[i], vv[j], O[i][j]);
        }
    }

    // Write output: out[b][q0 + r][d], normalized by l
    #pragma unroll
    for (int i = 0; i < 4; i++) {
        const float inv = 1.0f / l_[i];
        float4 v = make_float4(O[i][0] * inv, O[i][1] * inv,
                               O[i][2] * inv, O[i][3] * inv);
        *(float4*)&out[((size_t)b * T_ + q0 + ty * 4 + i) * H_ + tx * 4] = v;
    }
}

// ----------------------------------------------------------------------------
// Launch
// ----------------------------------------------------------------------------
extern "C" void kernel_launch(void* const* d_in, const int* in_sizes, int n_in,
                              void* d_out, int out_size)
{
    const float* emb = (const float*)d_in[0];
    const float* Wq  = (const float*)d_in[1];
    const float* Wk  = (const float*)d_in[2];
    const float* Wv  = (const float*)d_in[3];
    float* out = (float*)d_out;

    // Projection: grid (M/BM, 3)
    dim3 pg(MROWS / BM, 3, 1);
    proj_kernel<<<pg, 256>>>(emb, Wq, Wk, Wv);

    // Attention: grid (T/64, B), dynamic smem 4 * 64 * 68 * 4 bytes
    const int smem_bytes = 4 * 64 * AW * (int)sizeof(float);
    cudaFuncSetAttribute(attn_kernel, cudaFuncAttributeMaxDynamicSharedMemorySize,
                         smem_bytes);
    dim3 ag(T_ / 64, B_, 1);
    attn_kernel<<<ag, 256, smem_bytes>>>(out);
}

// round 3
// speedup vs baseline: 1.0041x; 1.0041x over previous
#include <cuda_runtime.h>
#include <math.h>

// ============================================================================
// AttentionHead: B=4, T=4096, E=1024, H=64, fp32, causal, scale = E^-0.5 = 1/32
// Round 1: fp32 SIMT baseline. Kernel 1: QKV projection SGEMM.
//          Kernel 2: flash-attention (online softmax), 64x64 tiles.
// ============================================================================

#define B_   4
#define T_   4096
#define E_   1024
#define H_   64
#define MROWS (B_ * T_)          // 16384

// scratch for q, k, v: [B*T][H] each
__device__ float g_q[MROWS * H_];
__device__ float g_k[MROWS * H_];
__device__ float g_v[MROWS * H_];

// ----------------------------------------------------------------------------
// Projection: C[m][n] = sum_e emb[m][e] * W[n][e]     (M=16384, N=64, K=1024)
// Tile: BM=128, BN=64, BK=16. 256 threads, 8x4 microtile per thread.
// grid.y in {0,1,2} selects Wq/Wk/Wv and output buffer.
// ----------------------------------------------------------------------------
#define BM 128
#define BN 64
#define BKP 16
#define AW_A (BM + 4)   // 132, multiple of 4 (float4-aligned rows)
#define AW_B (BN + 4)   // 68

__global__ __launch_bounds__(256) void proj_kernel(
    const float* __restrict__ emb,
    const float* __restrict__ Wq,
    const float* __restrict__ Wk,
    const float* __restrict__ Wv)
{
    __shared__ float As[BKP][AW_A];   // k-major: As[k][m]
    __shared__ float Bs[BKP][AW_B];   // k-major: Bs[k][n]

    const float* W = (blockIdx.y == 0) ? Wq : (blockIdx.y == 1) ? Wk : Wv;
    float* out     = (blockIdx.y == 0) ? g_q : (blockIdx.y == 1) ? g_k : g_v;

    const int tid = threadIdx.x;
    const int tx  = tid & 15;
    const int ty  = tid >> 4;
    const int row0 = blockIdx.x * BM;

    float acc[8][4];
    #pragma unroll
    for (int i = 0; i < 8; i++)
        #pragma unroll
        for (int j = 0; j < 4; j++) acc[i][j] = 0.0f;

    for (int k0 = 0; k0 < E_; k0 += BKP) {
        // Load A tile (128x16) transposed into As[k][m]: 512 float4, 2/thread
        #pragma unroll
        for (int it = 0; it < 2; it++) {
            int f  = tid + it * 256;
            int m  = f >> 2;         // 4 float4 per row (16 floats)
            int kv = f & 3;
            float4 v = *(const float4*)&emb[(size_t)(row0 + m) * E_ + k0 + kv * 4];
            As[kv * 4 + 0][m] = v.x;
            As[kv * 4 + 1][m] = v.y;
            As[kv * 4 + 2][m] = v.z;
            As[kv * 4 + 3][m] = v.w;
        }
        // Load B tile (64x16) transposed into Bs[k][n]: 256 float4, 1/thread
        {
            int n  = tid >> 2;
            int kv = tid & 3;
            float4 v = *(const float4*)&W[(size_t)n * E_ + k0 + kv * 4];
            Bs[kv * 4 + 0][n] = v.x;
            Bs[kv * 4 + 1][n] = v.y;
            Bs[kv * 4 + 2][n] = v.z;
            Bs[kv * 4 + 3][n] = v.w;
        }
        __syncthreads();

        #pragma unroll
        for (int kk = 0; kk < BKP; kk++) {
            float4 a0 = *(const float4*)&As[kk][ty * 8];
            float4 a1 = *(const float4*)&As[kk][ty * 8 + 4];
            float4 b0 = *(const float4*)&Bs[kk][tx * 4];
            float a[8] = {a0.x, a0.y, a0.z, a0.w, a1.x, a1.y, a1.z, a1.w};
            float bb[4] = {b0.x, b0.y, b0.z, b0.w};
            #pragma unroll
            for (int i = 0; i < 8; i++)
                #pragma unroll
                for (int j = 0; j < 4; j++)
                    acc[i][j] = fmaf(a[i], bb[j], acc[i][j]);
        }
        __syncthreads();
    }

    // Store: rows ty*8+i, cols tx*4..tx*4+3
    #pragma unroll
    for (int i = 0; i < 8; i++) {
        int m = row0 + ty * 8 + i;
        float4 v = make_float4(acc[i][0], acc[i][1], acc[i][2], acc[i][3]);
        *(float4*)&out[(size_t)m * H_ + tx * 4] = v;
    }
}

// ----------------------------------------------------------------------------
// Flash attention: per block, 64 queries of one batch; loop over causal key
// tiles of 64. 256 threads (16x16), 4x4 microtile.
// Smem (dynamic, 69632 B): Qt[64][68] (dim-major), Kt[64][68] (dim-major),
// Vs[64][68] (key-major), Pt[64][68] ([key][row]).
// ----------------------------------------------------------------------------
#define AW 68
#define NEG_INF (-1e30f)

__global__ __launch_bounds__(256) void attn_kernel(float* __restrict__ out)
{
    extern __shared__ float sm[];
    float (*Qt)[AW] = (float (*)[AW])(sm);                 // [dim][row]
    float (*Kt)[AW] = (float (*)[AW])(sm + 64 * AW);       // [dim][key]
    float (*Vs)[AW] = (float (*)[AW])(sm + 2 * 64 * AW);   // [key][dim]
    float (*Pt)[AW] = (float (*)[AW])(sm + 3 * 64 * AW);   // [key][row]

    const int tid = threadIdx.x;
    const int tx  = tid & 15;
    const int ty  = tid >> 4;
    const int b   = blockIdx.y;
    // Reverse so heaviest (most key tiles) blocks launch first
    const int qt  = gridDim.x - 1 - blockIdx.x;
    const int q0  = qt * 64;

    const float* qb = g_q + ((size_t)b * T_ + q0) * H_;
    const float* kb = g_k + (size_t)b * T_ * H_;
    const float* vb = g_v + (size_t)b * T_ * H_;

    // Load Q tile transposed: Qt[dim][row]
    #pragma unroll
    for (int it = 0; it < 4; it++) {
        int f  = tid + it * 256;
        int r  = f >> 4;        // 16 float4 per row
        int dv = f & 15;
        float4 v = *(const float4*)&qb[(size_t)r * H_ + dv * 4];
        Qt[dv * 4 + 0][r] = v.x;
        Qt[dv * 4 + 1][r] = v.y;
        Qt[dv * 4 + 2][r] = v.z;
        Qt[dv * 4 + 3][r] = v.w;
    }

    float m_[4], l_[4], O[4][4];
    #pragma unroll
    for (int i = 0; i < 4; i++) {
        m_[i] = NEG_INF;
        l_[i] = 0.0f;
        #pragma unroll
        for (int j = 0; j < 4; j++) O[i][j] = 0.0f;
    }

    const float scale = 0.03125f;  // E^-0.5 = 1/32
    const int ntiles = qt + 1;

    for (int t = 0; t < ntiles; t++) {
        const int k0 = t * 64;
        __syncthreads();  // prior GEMM1 (Kt) / GEMM2 (Vs, Pt) reads complete

        // Load K tile transposed + V tile natural
        #pragma unroll
        for (int it = 0; it < 4; it++) {
            int f  = tid + it * 256;
            int r  = f >> 4;
            int dv = f & 15;
            float4 v = *(const float4*)&kb[(size_t)(k0 + r) * H_ + dv * 4];
            Kt[dv * 4 + 0][r] = v.x;
            Kt[dv * 4 + 1][r] = v.y;
            Kt[dv * 4 + 2][r] = v.z;
            Kt[dv * 4 + 3][r] = v.w;
            float4 w = *(const float4*)&vb[(size_t)(k0 + r) * H_ + dv * 4];
            *(float4*)&Vs[r][dv * 4] = w;
        }
        __syncthreads();

        // GEMM1: S[r][c] = sum_d Q[r][d] * K[c][d]
        float S[4][4];
        #pragma unroll
        for (int i = 0; i < 4; i++)
            #pragma unroll
            for (int j = 0; j < 4; j++) S[i][j] = 0.0f;

        #pragma unroll 16
        for (int kk = 0; kk < 64; kk++) {
            float4 a  = *(const float4*)&Qt[kk][ty * 4];
            float4 b4 = *(const float4*)&Kt[kk][tx * 4];
            float av[4] = {a.x, a.y, a.z, a.w};
            float bv[4] = {b4.x, b4.y, b4.z, b4.w};
            #pragma unroll
            for (int i = 0; i < 4; i++)
                #pragma unroll
                for (int j = 0; j < 4; j++)
                    S[i][j] = fmaf(av[i], bv[j], S[i][j]);
        }

        // Scale, causal mask, online softmax update
        #pragma unroll
        for (int i = 0; i < 4; i++) {
            const int qg = q0 + ty * 4 + i;
            float mx = NEG_INF;
            #pragma unroll
            for (int j = 0; j < 4; j++) {
                const int kg = k0 + tx * 4 + j;
                float s = (kg <= qg) ? S[i][j] * scale : NEG_INF;
                S[i][j] = s;
                mx = fmaxf(mx, s);
            }
            // reduce max over the 16 tx lanes (lane bits 0..3)
            #pragma unroll
            for (int d = 1; d < 16; d <<= 1)
                mx = fmaxf(mx, __shfl_xor_sync(0xffffffffu, mx, d));
            const float mnew = fmaxf(m_[i], mx);
            const float al = __expf(m_[i] - mnew);
            float rs = 0.0f;
            #pragma unroll
            for (int j = 0; j < 4; j++) {
                float p = __expf(S[i][j] - mnew);
                S[i][j] = p;
                rs += p;
            }
            #pragma unroll
            for (int d = 1; d < 16; d <<= 1)
                rs += __shfl_xor_sync(0xffffffffu, rs, d);
            l_[i] = l_[i] * al + rs;
            m_[i] = mnew;
            #pragma unroll
            for (int j = 0; j < 4; j++) O[i][j] *= al;
        }

        // Store P transposed: Pt[key][row]
        #pragma unroll
        for (int i = 0; i < 4; i++)
            #pragma unroll
            for (int j = 0; j < 4; j++)
                Pt[tx * 4 + j][ty * 4 + i] = S[i][j];
        __syncthreads();

        // GEMM2: O[r][d] += sum_k P[r][k] * V[k][d]
        #pragma unroll 16
        for (int kk = 0; kk < 64; kk++) {
            float4 a  = *(const float4*)&Pt[kk][ty * 4];
            float4 v4 = *(const float4*)&Vs[kk][tx * 4];
            float av[4] = {a.x, a.y, a.z, a.w};
            float vv[4] = {v4.x, v4.y, v4.z, v4.w};
            #pragma unroll
            for (int i = 0; i < 4; i++)
                #pragma unroll
                for (int j = 0; j < 4; j++)
                    O[i][j] = fmaf(av[i], vv[j], O[i][j]);
        }
    }

    // Write output: out[b][q0 + r][d], normalized by l
    #pragma unroll
    for (int i = 0; i < 4; i++) {
        const float inv = 1.0f / l_[i];
        float4 v = make_float4(O[i][0] * inv, O[i][1] * inv,
                               O[i][2] * inv, O[i][3] * inv);
        *(float4*)&out[((size_t)b * T_ + q0 + ty * 4 + i) * H_ + tx * 4] = v;
    }
}

// ----------------------------------------------------------------------------
// Launch
// ----------------------------------------------------------------------------
extern "C" void kernel_launch(void* const* d_in, const int* in_sizes, int n_in,
                              void* d_out, int out_size)
{
    const float* emb = (const float*)d_in[0];
    const float* Wq  = (const float*)d_in[1];
    const float* Wk  = (const float*)d_in[2];
    const float* Wv  = (const float*)d_in[3];
    float* out = (float*)d_out;

    // Projection: grid (M/BM, 3)
    dim3 pg(MROWS / BM, 3, 1);
    proj_kernel<<<pg, 256>>>(emb, Wq, Wk, Wv);

    // Attention: grid (T/64, B), dynamic smem 4 * 64 * 68 * 4 bytes
    const int smem_bytes = 4 * 64 * AW * (int)sizeof(float);
    cudaFuncSetAttribute(attn_kernel, cudaFuncAttributeMaxDynamicSharedMemorySize,
                         smem_bytes);
    dim3 ag(T_ / 64, B_, 1);
    attn_kernel<<<ag, 256, smem_bytes>>>(out);
}

// round 6
// speedup vs baseline: 2.1189x; 2.1103x over previous
#include <cuda_runtime.h>
#include <cuda_bf16.h>
#include <cstdint>

#define B_    4
#define T_    4096
#define E_    1024
#define MROWS (B_ * T_)
#define CL2   0.045084220f   // (1/32) * log2(e)

// hi/lo bf16 planes produced by projection
__device__ __nv_bfloat16 g_qh[MROWS * 64], g_ql[MROWS * 64];
__device__ __nv_bfloat16 g_kh[MROWS * 64], g_kl[MROWS * 64];
// V transposed: [b][d][t]
__device__ __nv_bfloat16 g_vth[B_ * 64 * T_], g_vtl[B_ * 64 * T_];

// ---------------------------------------------------------------------------
__device__ __forceinline__ void hmma(float* c, const uint32_t* a,
                                     uint32_t b0, uint32_t b1) {
    asm volatile("mma.sync.aligned.m16n8k16.row.col.f32.bf16.bf16.f32 "
                 "{%0,%1,%2,%3}, {%4,%5,%6,%7}, {%8,%9}, {%0,%1,%2,%3};"
                 : "+f"(c[0]), "+f"(c[1]), "+f"(c[2]), "+f"(c[3])
                 : "r"(a[0]), "r"(a[1]), "r"(a[2]), "r"(a[3]),
                   "r"(b0), "r"(b1));
}
__device__ __forceinline__ uint32_t bfpack(float a, float b) {
    __nv_bfloat162 h(__float2bfloat16(a), __float2bfloat16(b));
    return *(uint32_t*)&h;
}
__device__ __forceinline__ float bflo(float x) {
    return x - __bfloat162float(__float2bfloat16(x));
}
__device__ __forceinline__ float ex2(float x) {
    float y; asm("ex2.approx.f32 %0, %1;" : "=f"(y) : "f"(x)); return y;
}

// ---------------------------------------------------------------------------
// Projection: C[m][n] = sum_e emb[m][e] * W[n][e]. M=16384, N=64, K=1024.
// grid (128, 3): blockIdx.y selects W / output set. 128 threads (4 warps),
// warp computes 32 rows (2 m16 tiles) x 64 cols. K-chunks of 64.
// smem (dynamic, 55296 B): Ah/Al [128][72], Bh/Bl [64][72] bf16.
// ---------------------------------------------------------------------------
#define PST 72

__global__ __launch_bounds__(128) void proj_kernel(
    const float* __restrict__ emb, const float* __restrict__ Wq,
    const float* __restrict__ Wk, const float* __restrict__ Wv)
{
    extern __shared__ __nv_bfloat16 psm[];
    __nv_bfloat16* Ah = psm;
    __nv_bfloat16* Al = psm + 128 * PST;
    __nv_bfloat16* Bh = psm + 2 * 128 * PST;
    __nv_bfloat16* Bl = Bh + 64 * PST;

    const int tid = threadIdx.x, lane = tid & 31, wid = tid >> 5;
    const int g = lane >> 2, tg = lane & 3;
    const int row0 = blockIdx.x * 128;
    const int wsel = blockIdx.y;
    const float* W = (wsel == 0) ? Wq : (wsel == 1) ? Wk : Wv;

    float acc[2][8][4];
    #pragma unroll
    for (int mi = 0; mi < 2; mi++)
        #pragma unroll
        for (int j = 0; j < 8; j++)
            #pragma unroll
            for (int e = 0; e < 4; e++) acc[mi][j][e] = 0.0f;

    for (int ch = 0; ch < 16; ch++) {
        const int k0 = ch * 64;
        __syncthreads();
        // A tile 128x64 fp32 -> hi/lo planes. 2048 float4, 16 per thread.
        #pragma unroll
        for (int it = 0; it < 16; it++) {
            int idx = tid + it * 128;
            int r = idx >> 4, f = idx & 15;
            float4 v = *(const float4*)&emb[(size_t)(row0 + r) * E_ + k0 + f * 4];
            *(uint2*)&Ah[r * PST + f * 4] =
                make_uint2(bfpack(v.x, v.y), bfpack(v.z, v.w));
            *(uint2*)&Al[r * PST + f * 4] =
                make_uint2(bfpack(bflo(v.x), bflo(v.y)), bfpack(bflo(v.z), bflo(v.w)));
        }
        // W tile 64x64 fp32. 1024 float4, 8 per thread.
        #pragma unroll
        for (int it = 0; it < 8; it++) {
            int idx = tid + it * 128;
            int r = idx >> 4, f = idx & 15;
            float4 v = *(const float4*)&W[(size_t)r * E_ + k0 + f * 4];
            *(uint2*)&Bh[r * PST + f * 4] =
                make_uint2(bfpack(v.x, v.y), bfpack(v.z, v.w));
            *(uint2*)&Bl[r * PST + f * 4] =
                make_uint2(bfpack(bflo(v.x), bflo(v.y)), bfpack(bflo(v.z), bflo(v.w)));
        }
        __syncthreads();

        #pragma unroll
        for (int kc = 0; kc < 4; kc++) {
            const int c = kc * 16 + tg * 2;
            uint32_t ah[2][4], al[2][4];
            #pragma unroll
            for (int mi = 0; mi < 2; mi++) {
                const int rr = wid * 32 + mi * 16 + g;
                ah[mi][0] = *(uint32_t*)&Ah[rr * PST + c];
                ah[mi][1] = *(uint32_t*)&Ah[(rr + 8) * PST + c];
                ah[mi][2] = *(uint32_t*)&Ah[rr * PST + c + 8];
                ah[mi][3] = *(uint32_t*)&Ah[(rr + 8) * PST + c + 8];
                al[mi][0] = *(uint32_t*)&Al[rr * PST + c];
                al[mi][1] = *(uint32_t*)&Al[(rr + 8) * PST + c];
                al[mi][2] = *(uint32_t*)&Al[rr * PST + c + 8];
                al[mi][3] = *(uint32_t*)&Al[(rr + 8) * PST + c + 8];
            }
            #pragma unroll
            for (int j = 0; j < 8; j++) {
                const int bn = (j * 8 + g) * PST + c;
                uint32_t bh0 = *(uint32_t*)&Bh[bn];
                uint32_t bh1 = *(uint32_t*)&Bh[bn + 8];
                uint32_t bl0 = *(uint32_t*)&Bl[bn];
                uint32_t bl1 = *(uint32_t*)&Bl[bn + 8];
                #pragma unroll
                for (int mi = 0; mi < 2; mi++) {
                    hmma(acc[mi][j], ah[mi], bh0, bh1);
                    hmma(acc[mi][j], ah[mi], bl0, bl1);
                    hmma(acc[mi][j], al[mi], bh0, bh1);
                }
            }
        }
    }

    // Epilogue
    #pragma unroll
    for (int mi = 0; mi < 2; mi++) {
        #pragma unroll
        for (int half = 0; half < 2; half++) {
            const int row = row0 + wid * 32 + mi * 16 + g + half * 8;
            #pragma unroll
            for (int j = 0; j < 8; j++) {
                const float x0 = acc[mi][j][half * 2 + 0];
                const float x1 = acc[mi][j][half * 2 + 1];
                const int d = j * 8 + tg * 2;
                if (wsel < 2) {
                    __nv_bfloat16* gh = (wsel == 0) ? g_qh : g_kh;
                    __nv_bfloat16* gl = (wsel == 0) ? g_ql : g_kl;
                    *(uint32_t*)&gh[(size_t)row * 64 + d] = bfpack(x0, x1);
                    *(uint32_t*)&gl[(size_t)row * 64 + d] = bfpack(bflo(x0), bflo(x1));
                } else {
                    const int b = row >> 12, t = row & (T_ - 1);
                    g_vth[(size_t)(b * 64 + d) * T_ + t]     = __float2bfloat16(x0);
                    g_vth[(size_t)(b * 64 + d + 1) * T_ + t] = __float2bfloat16(x1);
                    g_vtl[(size_t)(b * 64 + d) * T_ + t]     = __float2bfloat16(bflo(x0));
                    g_vtl[(size_t)(b * 64 + d + 1) * T_ + t] = __float2bfloat16(bflo(x1));
                }
            }
        }
    }
}

// ---------------------------------------------------------------------------
// Flash attention: grid (32, 4), 256 threads (8 warps). CTA = 128 q rows,
// warp = 16 rows. Key tiles of 64. Q frags in registers; K/V^T tiles in smem.
// ---------------------------------------------------------------------------
#define KST 72

__global__ __launch_bounds__(256) void attn_kernel(float* __restrict__ out)
{
    __shared__ __nv_bfloat16 Kh[64 * KST], Kl[64 * KST];
    __shared__ __nv_bfloat16 Vh[64 * KST], Vl[64 * KST];

    const int tid = threadIdx.x, lane = tid & 31, wid = tid >> 5;
    const int g = lane >> 2, tg = lane & 3;
    const int b = blockIdx.y;
    const int qt = gridDim.x - 1 - blockIdx.x;   // heavy CTAs first
    const int q0 = qt * 128;
    const size_t bT = (size_t)b * T_;
    const int r0 = q0 + wid * 16 + g;            // this thread's base row

    // Hoist Q fragments (hi and lo) for all 4 k-chunks
    uint32_t qfh[4][4], qfl[4][4];
    #pragma unroll
    for (int kc = 0; kc < 4; kc++) {
        const int c = kc * 16 + tg * 2;
        const size_t p0 = (bT + r0) * 64 + c;
        const size_t p1 = (bT + r0 + 8) * 64 + c;
        qfh[kc][0] = *(const uint32_t*)&g_qh[p0];
        qfh[kc][1] = *(const uint32_t*)&g_qh[p1];
        qfh[kc][2] = *(const uint32_t*)&g_qh[p0 + 8];
        qfh[kc][3] = *(const uint32_t*)&g_qh[p1 + 8];
        qfl[kc][0] = *(const uint32_t*)&g_ql[p0];
        qfl[kc][1] = *(const uint32_t*)&g_ql[p1];
        qfl[kc][2] = *(const uint32_t*)&g_ql[p0 + 8];
        qfl[kc][3] = *(const uint32_t*)&g_ql[p1 + 8];
    }

    float O[8][4];
    #pragma unroll
    for (int j = 0; j < 8; j++)
        #pragma unroll
        for (int e = 0; e < 4; e++) O[j][e] = 0.0f;
    float m0 = -1e30f, m1 = -1e30f, l0 = 0.0f, l1 = 0.0f;

    const int nt = 2 * qt + 2;
    for (int t = 0; t < nt; t++) {
        const int k0 = t * 64;
        __syncthreads();
        // Load K (hi/lo) and V^T (hi/lo) tiles: 512 float4 per plane.
        #pragma unroll
        for (int it = 0; it < 2; it++) {
            int idx = tid + it * 256;
            int r = idx >> 3, f = idx & 7;
            *(float4*)&Kh[r * KST + f * 8] =
                *(const float4*)&g_kh[(bT + k0 + r) * 64 + f * 8];
            *(float4*)&Kl[r * KST + f * 8] =
                *(const float4*)&g_kl[(bT + k0 + r) * 64 + f * 8];
            *(float4*)&Vh[r * KST + f * 8] =
                *(const float4*)&g_vth[(size_t)(b * 64 + r) * T_ + k0 + f * 8];
            *(float4*)&Vl[r * KST + f * 8] =
                *(const float4*)&g_vtl[(size_t)(b * 64 + r) * T_ + k0 + f * 8];
        }
        __syncthreads();

        // GEMM1: S = Q . K^T (3 hi/lo terms)
        float S[8][4];
        #pragma unroll
        for (int j = 0; j < 8; j++)
            #pragma unroll
            for (int e = 0; e < 4; e++) S[j][e] = 0.0f;
        #pragma unroll
        for (int kc = 0; kc < 4; kc++) {
            const int c = kc * 16 + tg * 2;
            #pragma unroll
            for (int j = 0; j < 8; j++) {
                const int bn = (j * 8 + g) * KST + c;
                uint32_t bh0 = *(uint32_t*)&Kh[bn];
                uint32_t bh1 = *(uint32_t*)&Kh[bn + 8];
                uint32_t bl0 = *(uint32_t*)&Kl[bn];
                uint32_t bl1 = *(uint32_t*)&Kl[bn + 8];
                hmma(S[j], qfh[kc], bh0, bh1);
                hmma(S[j], qfh[kc], bl0, bl1);
                hmma(S[j], qfl[kc], bh0, bh1);
            }
        }

        // Softmax (exp2 domain), causal mask on diagonal tiles
        const bool diag = (k0 + 63 > q0);
        float mx0 = -1e30f, mx1 = -1e30f;
        #pragma unroll
        for (int j = 0; j < 8; j++) {
            #pragma unroll
            for (int e = 0; e < 2; e++) {
                const int kg = k0 + j * 8 + tg * 2 + e;
                float z0 = S[j][e] * CL2;
                float z1 = S[j][2 + e] * CL2;
                if (diag) {
                    if (kg > r0)     z0 = -1e30f;
                    if (kg > r0 + 8) z1 = -1e30f;
                }
                S[j][e] = z0; S[j][2 + e] = z1;
                mx0 = fmaxf(mx0, z0); mx1 = fmaxf(mx1, z1);
            }
        }
        mx0 = fmaxf(mx0, __shfl_xor_sync(0xffffffffu, mx0, 1));
        mx0 = fmaxf(mx0, __shfl_xor_sync(0xffffffffu, mx0, 2));
        mx1 = fmaxf(mx1, __shfl_xor_sync(0xffffffffu, mx1, 1));
        mx1 = fmaxf(mx1, __shfl_xor_sync(0xffffffffu, mx1, 2));
        const float mn0 = fmaxf(m0, mx0), mn1 = fmaxf(m1, mx1);
        const float a0 = ex2(m0 - mn0), a1 = ex2(m1 - mn1);
        m0 = mn0; m1 = mn1;
        float rs0 = 0.0f, rs1 = 0.0f;
        #pragma unroll
        for (int j = 0; j < 8; j++) {
            #pragma unroll
            for (int e = 0; e < 2; e++) {
                float p0 = ex2(S[j][e] - mn0);
                float p1 = ex2(S[j][2 + e] - mn1);
                S[j][e] = p0; S[j][2 + e] = p1;
                rs0 += p0; rs1 += p1;
            }
        }
        rs0 += __shfl_xor_sync(0xffffffffu, rs0, 1);
        rs0 += __shfl_xor_sync(0xffffffffu, rs0, 2);
        rs1 += __shfl_xor_sync(0xffffffffu, rs1, 1);
        rs1 += __shfl_xor_sync(0xffffffffu, rs1, 2);
        l0 = l0 * a0 + rs0;
        l1 = l1 * a1 + rs1;
        #pragma unroll
        for (int j = 0; j < 8; j++) {
            O[j][0] *= a0; O[j][1] *= a0;
            O[j][2] *= a1; O[j][3] *= a1;
        }

        // P accum -> A fragments (hi/lo)
        uint32_t pfh[4][4], pfl[4][4];
        #pragma unroll
        for (int kc = 0; kc < 4; kc++) {
            const int j0 = 2 * kc, j1 = 2 * kc + 1;
            pfh[kc][0] = bfpack(S[j0][0], S[j0][1]);
            pfh[kc][1] = bfpack(S[j0][2], S[j0][3]);
            pfh[kc][2] = bfpack(S[j1][0], S[j1][1]);
            pfh[kc][3] = bfpack(S[j1][2], S[j1][3]);
            pfl[kc][0] = bfpack(bflo(S[j0][0]), bflo(S[j0][1]));
            pfl[kc][1] = bfpack(bflo(S[j0][2]), bflo(S[j0][3]));
            pfl[kc][2] = bfpack(bflo(S[j1][0]), bflo(S[j1][1]));
            pfl[kc][3] = bfpack(bflo(S[j1][2]), bflo(S[j1][3]));
        }

        // GEMM2: O += P . V (3 hi/lo terms)
        #pragma unroll
        for (int kc = 0; kc < 4; kc++) {
            const int c = kc * 16 + tg * 2;
            #pragma unroll
            for (int j = 0; j < 8; j++) {
                const int bn = (j * 8 + g) * KST + c;
                uint32_t bh0 = *(uint32_t*)&Vh[bn];
                uint32_t bh1 = *(uint32_t*)&Vh[bn + 8];
                uint32_t bl0 = *(uint32_t*)&Vl[bn];
                uint32_t bl1 = *(uint32_t*)&Vl[bn + 8];
                hmma(O[j], pfh[kc], bh0, bh1);
                hmma(O[j], pfh[kc], bl0, bl1);
                hmma(O[j], pfl[kc], bh0, bh1);
            }
        }
    }

    // Epilogue: normalize and store
    const float inv0 = 1.0f / l0, inv1 = 1.0f / l1;
    #pragma unroll
    for (int j = 0; j < 8; j++) {
        const int d = j * 8 + tg * 2;
        float2 v0 = make_float2(O[j][0] * inv0, O[j][1] * inv0);
        float2 v1 = make_float2(O[j][2] * inv1, O[j][3] * inv1);
        *(float2*)&out[(bT + r0) * 64 + d]     = v0;
        *(float2*)&out[(bT + r0 + 8) * 64 + d] = v1;
    }
}

// ---------------------------------------------------------------------------
extern "C" void kernel_launch(void* const* d_in, const int* in_sizes, int n_in,
                              void* d_out, int out_size)
{
    const float* emb = (const float*)d_in[0];
    const float* Wq  = (const float*)d_in[1];
    const float* Wk  = (const float*)d_in[2];
    const float* Wv  = (const float*)d_in[3];
    float* out = (float*)d_out;

    const int psmem = (2 * 128 * PST + 2 * 64 * PST) * (int)sizeof(__nv_bfloat16);
    cudaFuncSetAttribute(proj_kernel, cudaFuncAttributeMaxDynamicSharedMemorySize,
                         psmem);
    dim3 pg(MROWS / 128, 3, 1);
    proj_kernel<<<pg, 128, psmem>>>(emb, Wq, Wk, Wv);

    dim3 ag(T_ / 128, B_, 1);
    attn_kernel<<<ag, 256>>>(out);
}

// round 7
// speedup vs baseline: 3.4360x; 1.6216x over previous
#include <cuda_runtime.h>
#include <cuda_bf16.h>
#include <cstdint>

#define B_    4
#define T_    4096
#define E_    1024
#define MROWS (B_ * T_)
#define CL2   0.045084220f   // (1/32) * log2(e)

// hi/lo bf16 planes produced by projection
__device__ __nv_bfloat16 g_qh[MROWS * 64], g_ql[MROWS * 64];
__device__ __nv_bfloat16 g_kh[MROWS * 64], g_kl[MROWS * 64];
// V transposed: [b][d][t]
__device__ __nv_bfloat16 g_vth[B_ * 64 * T_], g_vtl[B_ * 64 * T_];
// split-K partials: slot = (b*64 + qt)*8 + c
__device__ float g_po[2048 * 64 * 64];     // unnormalized O per slot
__device__ float g_pml[2048 * 128];        // per row: m (log2 domain), l

// ---------------------------------------------------------------------------
__device__ __forceinline__ void hmma(float* c, const uint32_t* a,
                                     uint32_t b0, uint32_t b1) {
    asm volatile("mma.sync.aligned.m16n8k16.row.col.f32.bf16.bf16.f32 "
                 "{%0,%1,%2,%3}, {%4,%5,%6,%7}, {%8,%9}, {%0,%1,%2,%3};"
                 : "+f"(c[0]), "+f"(c[1]), "+f"(c[2]), "+f"(c[3])
                 : "r"(a[0]), "r"(a[1]), "r"(a[2]), "r"(a[3]),
                   "r"(b0), "r"(b1));
}
__device__ __forceinline__ uint32_t bfpack(float a, float b) {
    __nv_bfloat162 h(__float2bfloat16(a), __float2bfloat16(b));
    return *(uint32_t*)&h;
}
__device__ __forceinline__ float bflo(float x) {
    return x - __bfloat162float(__float2bfloat16(x));
}
__device__ __forceinline__ float ex2(float x) {
    float y; asm("ex2.approx.f32 %0, %1;" : "=f"(y) : "f"(x)); return y;
}

// ---------------------------------------------------------------------------
// Merged projection: C[m][n] = sum_e emb[m][e] * W[n][e] for Wq,Wk,Wv at once.
// grid 128, 256 threads (8 warps). Warp owns 16 rows x all 192 out cols.
// K-chunks of 64. smem: Ah/Al [128][72], Bh/Bl [192][72] bf16 (92160 B).
// ---------------------------------------------------------------------------
#define PST 72

__global__ __launch_bounds__(256) void proj_kernel(
    const float* __restrict__ emb, const float* __restrict__ Wq,
    const float* __restrict__ Wk, const float* __restrict__ Wv)
{
    extern __shared__ __nv_bfloat16 psm[];
    __nv_bfloat16* Ah = psm;
    __nv_bfloat16* Al = psm + 128 * PST;
    __nv_bfloat16* Bh = psm + 2 * 128 * PST;
    __nv_bfloat16* Bl = Bh + 192 * PST;

    const int tid = threadIdx.x, lane = tid & 31, wid = tid >> 5;
    const int gq = lane >> 2, tg = lane & 3;
    const int row0 = blockIdx.x * 128;

    float acc[24][4];
    #pragma unroll
    for (int j = 0; j < 24; j++)
        #pragma unroll
        for (int e = 0; e < 4; e++) acc[j][e] = 0.0f;

    for (int ch = 0; ch < 16; ch++) {
        const int k0 = ch * 64;
        __syncthreads();
        // A tile 128x64 fp32 -> hi/lo. 2048 float4, 8 per thread.
        #pragma unroll
        for (int it = 0; it < 8; it++) {
            int idx = tid + it * 256;
            int r = idx >> 4, f = idx & 15;
            float4 v = *(const float4*)&emb[(size_t)(row0 + r) * E_ + k0 + f * 4];
            *(uint2*)&Ah[r * PST + f * 4] =
                make_uint2(bfpack(v.x, v.y), bfpack(v.z, v.w));
            *(uint2*)&Al[r * PST + f * 4] =
                make_uint2(bfpack(bflo(v.x), bflo(v.y)), bfpack(bflo(v.z), bflo(v.w)));
        }
        // B tile 192x64 fp32 (Wq|Wk|Wv). 3072 float4, 12 per thread.
        #pragma unroll
        for (int it = 0; it < 12; it++) {
            int idx = tid + it * 256;
            int r = idx >> 4, f = idx & 15;
            const float* Wr = (r < 64) ? Wq : (r < 128) ? Wk : Wv;
            float4 v = *(const float4*)&Wr[(size_t)(r & 63) * E_ + k0 + f * 4];
            *(uint2*)&Bh[r * PST + f * 4] =
                make_uint2(bfpack(v.x, v.y), bfpack(v.z, v.w));
            *(uint2*)&Bl[r * PST + f * 4] =
                make_uint2(bfpack(bflo(v.x), bflo(v.y)), bfpack(bflo(v.z), bflo(v.w)));
        }
        __syncthreads();

        #pragma unroll
        for (int kc = 0; kc < 4; kc++) {
            const int c = kc * 16 + tg * 2;
            const int rr = wid * 16 + gq;
            uint32_t ah[4], al[4];
            ah[0] = *(uint32_t*)&Ah[rr * PST + c];
            ah[1] = *(uint32_t*)&Ah[(rr + 8) * PST + c];
            ah[2] = *(uint32_t*)&Ah[rr * PST + c + 8];
            ah[3] = *(uint32_t*)&Ah[(rr + 8) * PST + c + 8];
            al[0] = *(uint32_t*)&Al[rr * PST + c];
            al[1] = *(uint32_t*)&Al[(rr + 8) * PST + c];
            al[2] = *(uint32_t*)&Al[rr * PST + c + 8];
            al[3] = *(uint32_t*)&Al[(rr + 8) * PST + c + 8];
            #pragma unroll
            for (int j = 0; j < 24; j++) {
                const int bn = (j * 8 + gq) * PST + c;
                uint32_t bh0 = *(uint32_t*)&Bh[bn];
                uint32_t bh1 = *(uint32_t*)&Bh[bn + 8];
                uint32_t bl0 = *(uint32_t*)&Bl[bn];
                uint32_t bl1 = *(uint32_t*)&Bl[bn + 8];
                hmma(acc[j], ah, bh0, bh1);
                hmma(acc[j], ah, bl0, bl1);
                hmma(acc[j], al, bh0, bh1);
            }
        }
    }

    // Epilogue
    #pragma unroll
    for (int half = 0; half < 2; half++) {
        const int row = row0 + wid * 16 + gq + half * 8;
        const int b = row >> 12, t = row & (T_ - 1);
        #pragma unroll
        for (int j = 0; j < 24; j++) {
            const int wsel = j >> 3;
            const int d = (j & 7) * 8 + tg * 2;
            const float x0 = acc[j][half * 2 + 0];
            const float x1 = acc[j][half * 2 + 1];
            if (wsel < 2) {
                __nv_bfloat16* gh = (wsel == 0) ? g_qh : g_kh;
                __nv_bfloat16* gl = (wsel == 0) ? g_ql : g_kl;
                *(uint32_t*)&gh[(size_t)row * 64 + d] = bfpack(x0, x1);
                *(uint32_t*)&gl[(size_t)row * 64 + d] = bfpack(bflo(x0), bflo(x1));
            } else {
                g_vth[(size_t)(b * 64 + d) * T_ + t]     = __float2bfloat16(x0);
                g_vth[(size_t)(b * 64 + d + 1) * T_ + t] = __float2bfloat16(x1);
                g_vtl[(size_t)(b * 64 + d) * T_ + t]     = __float2bfloat16(bflo(x0));
                g_vtl[(size_t)(b * 64 + d + 1) * T_ + t] = __float2bfloat16(bflo(x1));
            }
        }
    }
}

// ---------------------------------------------------------------------------
// Flash attention, split-K units. grid 1152 = 4 batches x 288 units.
// Unit = (b, qt 64-row q-block, chunk c of <=8 key-tiles of 64).
// 128 threads (4 warps), warp = 16 rows. Writes partial (O, m, l).
// ---------------------------------------------------------------------------
#define KST 72

__global__ __launch_bounds__(128) void attn_kernel()
{
    __shared__ __nv_bfloat16 Kh[64 * KST], Kl[64 * KST];
    __shared__ __nv_bfloat16 Vh[64 * KST], Vl[64 * KST];

    const int tid = threadIdx.x, lane = tid & 31, wid = tid >> 5;
    const int gq = lane >> 2, tg = lane & 3;

    // decode unit
    const int u = blockIdx.x;
    const int b = u / 288;
    const int r = u - b * 288;
    int gg = 0;
    #pragma unroll
    for (int i = 1; i < 8; i++) if (r >= 4 * i * (i + 1)) gg = i;
    const int off = r - 4 * gg * (gg + 1);
    const int blk = off / (gg + 1);
    const int c   = off - blk * (gg + 1);
    const int qt  = 8 * gg + blk;
    const int t0  = c * 8;
    const int t1  = min(t0 + 8, qt + 1);
    const int q0  = qt * 64;
    const size_t bT = (size_t)b * T_;
    const int rloc = wid * 16 + gq;       // row in q-block (0..63)
    const int r0 = q0 + rloc;             // global q row

    // Hoist Q fragments (hi and lo) for all 4 k-chunks
    uint32_t qfh[4][4], qfl[4][4];
    #pragma unroll
    for (int kc = 0; kc < 4; kc++) {
        const int cc = kc * 16 + tg * 2;
        const size_t p0 = (bT + r0) * 64 + cc;
        const size_t p1 = (bT + r0 + 8) * 64 + cc;
        qfh[kc][0] = *(const uint32_t*)&g_qh[p0];
        qfh[kc][1] = *(const uint32_t*)&g_qh[p1];
        qfh[kc][2] = *(const uint32_t*)&g_qh[p0 + 8];
        qfh[kc][3] = *(const uint32_t*)&g_qh[p1 + 8];
        qfl[kc][0] = *(const uint32_t*)&g_ql[p0];
        qfl[kc][1] = *(const uint32_t*)&g_ql[p1];
        qfl[kc][2] = *(const uint32_t*)&g_ql[p0 + 8];
        qfl[kc][3] = *(const uint32_t*)&g_ql[p1 + 8];
    }

    float O[8][4];
    #pragma unroll
    for (int j = 0; j < 8; j++)
        #pragma unroll
        for (int e = 0; e < 4; e++) O[j][e] = 0.0f;
    float m0 = -1e30f, m1 = -1e30f, l0 = 0.0f, l1 = 0.0f;

    for (int t = t0; t < t1; t++) {
        const int k0 = t * 64;
        __syncthreads();
        // K (hi/lo) + V^T (hi/lo) tiles: 512 float4 per plane, 4 per thread.
        #pragma unroll
        for (int it = 0; it < 4; it++) {
            int idx = tid + it * 128;
            int rr = idx >> 3, f = idx & 7;
            *(float4*)&Kh[rr * KST + f * 8] =
                *(const float4*)&g_kh[(bT + k0 + rr) * 64 + f * 8];
            *(float4*)&Kl[rr * KST + f * 8] =
                *(const float4*)&g_kl[(bT + k0 + rr) * 64 + f * 8];
            *(float4*)&Vh[rr * KST + f * 8] =
                *(const float4*)&g_vth[(size_t)(b * 64 + rr) * T_ + k0 + f * 8];
            *(float4*)&Vl[rr * KST + f * 8] =
                *(const float4*)&g_vtl[(size_t)(b * 64 + rr) * T_ + k0 + f * 8];
        }
        __syncthreads();

        // GEMM1: S = Q . K^T (3 hi/lo terms)
        float S[8][4];
        #pragma unroll
        for (int j = 0; j < 8; j++)
            #pragma unroll
            for (int e = 0; e < 4; e++) S[j][e] = 0.0f;
        #pragma unroll
        for (int kc = 0; kc < 4; kc++) {
            const int cc = kc * 16 + tg * 2;
            #pragma unroll
            for (int j = 0; j < 8; j++) {
                const int bn = (j * 8 + gq) * KST + cc;
                uint32_t bh0 = *(uint32_t*)&Kh[bn];
                uint32_t bh1 = *(uint32_t*)&Kh[bn + 8];
                uint32_t bl0 = *(uint32_t*)&Kl[bn];
                uint32_t bl1 = *(uint32_t*)&Kl[bn + 8];
                hmma(S[j], qfh[kc], bh0, bh1);
                hmma(S[j], qfh[kc], bl0, bl1);
                hmma(S[j], qfl[kc], bh0, bh1);
            }
        }

        // Softmax (exp2 domain); only tile t==qt is diagonal
        const bool diag = (t == qt);
        float mx0 = -1e30f, mx1 = -1e30f;
        #pragma unroll
        for (int j = 0; j < 8; j++) {
            #pragma unroll
            for (int e = 0; e < 2; e++) {
                const int kg = k0 + j * 8 + tg * 2 + e;
                float z0 = S[j][e] * CL2;
                float z1 = S[j][2 + e] * CL2;
                if (diag) {
                    if (kg > r0)     z0 = -1e30f;
                    if (kg > r0 + 8) z1 = -1e30f;
                }
                S[j][e] = z0; S[j][2 + e] = z1;
                mx0 = fmaxf(mx0, z0); mx1 = fmaxf(mx1, z1);
            }
        }
        mx0 = fmaxf(mx0, __shfl_xor_sync(0xffffffffu, mx0, 1));
        mx0 = fmaxf(mx0, __shfl_xor_sync(0xffffffffu, mx0, 2));
        mx1 = fmaxf(mx1, __shfl_xor_sync(0xffffffffu, mx1, 1));
        mx1 = fmaxf(mx1, __shfl_xor_sync(0xffffffffu, mx1, 2));
        const float mn0 = fmaxf(m0, mx0), mn1 = fmaxf(m1, mx1);
        const float a0 = ex2(m0 - mn0), a1 = ex2(m1 - mn1);
        m0 = mn0; m1 = mn1;
        float rs0 = 0.0f, rs1 = 0.0f;
        #pragma unroll
        for (int j = 0; j < 8; j++) {
            #pragma unroll
            for (int e = 0; e < 2; e++) {
                float p0 = ex2(S[j][e] - mn0);
                float p1 = ex2(S[j][2 + e] - mn1);
                S[j][e] = p0; S[j][2 + e] = p1;
                rs0 += p0; rs1 += p1;
            }
        }
        rs0 += __shfl_xor_sync(0xffffffffu, rs0, 1);
        rs0 += __shfl_xor_sync(0xffffffffu, rs0, 2);
        rs1 += __shfl_xor_sync(0xffffffffu, rs1, 1);
        rs1 += __shfl_xor_sync(0xffffffffu, rs1, 2);
        l0 = l0 * a0 + rs0;
        l1 = l1 * a1 + rs1;
        #pragma unroll
        for (int j = 0; j < 8; j++) {
            O[j][0] *= a0; O[j][1] *= a0;
            O[j][2] *= a1; O[j][3] *= a1;
        }

        // P accum -> A fragments (hi/lo)
        uint32_t pfh[4][4], pfl[4][4];
        #pragma unroll
        for (int kc = 0; kc < 4; kc++) {
            const int j0 = 2 * kc, j1 = 2 * kc + 1;
            pfh[kc][0] = bfpack(S[j0][0], S[j0][1]);
            pfh[kc][1] = bfpack(S[j0][2], S[j0][3]);
            pfh[kc][2] = bfpack(S[j1][0], S[j1][1]);
            pfh[kc][3] = bfpack(S[j1][2], S[j1][3]);
            pfl[kc][0] = bfpack(bflo(S[j0][0]), bflo(S[j0][1]));
            pfl[kc][1] = bfpack(bflo(S[j0][2]), bflo(S[j0][3]));
            pfl[kc][2] = bfpack(bflo(S[j1][0]), bflo(S[j1][1]));
            pfl[kc][3] = bfpack(bflo(S[j1][2]), bflo(S[j1][3]));
        }

        // GEMM2: O += P . V (3 hi/lo terms)
        #pragma unroll
        for (int kc = 0; kc < 4; kc++) {
            const int cc = kc * 16 + tg * 2;
            #pragma unroll
            for (int j = 0; j < 8; j++) {
                const int bn = (j * 8 + gq) * KST + cc;
                uint32_t bh0 = *(uint32_t*)&Vh[bn];
                uint32_t bh1 = *(uint32_t*)&Vh[bn + 8];
                uint32_t bl0 = *(uint32_t*)&Vl[bn];
                uint32_t bl1 = *(uint32_t*)&Vl[bn + 8];
                hmma(O[j], pfh[kc], bh0, bh1);
                hmma(O[j], pfh[kc], bl0, bl1);
                hmma(O[j], pfl[kc], bh0, bh1);
            }
        }
    }

    // Write partial: unnormalized O, plus (m, l) per row
    const int slot = (b * 64 + qt) * 8 + c;
    float* po = g_po + (size_t)slot * 4096;
    #pragma unroll
    for (int j = 0; j < 8; j++) {
        const int d = j * 8 + tg * 2;
        *(float2*)&po[rloc * 64 + d]       = make_float2(O[j][0], O[j][1]);
        *(float2*)&po[(rloc + 8) * 64 + d] = make_float2(O[j][2], O[j][3]);
    }
    if (tg == 0) {
        g_pml[slot * 128 + rloc * 2]           = m0;
        g_pml[slot * 128 + rloc * 2 + 1]       = l0;
        g_pml[slot * 128 + (rloc + 8) * 2]     = m1;
        g_pml[slot * 128 + (rloc + 8) * 2 + 1] = l1;
    }
}

// ---------------------------------------------------------------------------
// Combine: grid (64, 4), 256 threads. Thread = (row, 16-col segment).
// ---------------------------------------------------------------------------
__global__ __launch_bounds__(256) void combine_kernel(float* __restrict__ out)
{
    const int qt = blockIdx.x, b = blockIdx.y;
    const int nc = (qt >> 3) + 1;
    const int tid = threadIdx.x;
    const int row = tid >> 2, seg = (tid & 3) * 16;
    const int bs = (b * 64 + qt) * 8;

    float M = -1e30f;
    for (int c = 0; c < nc; c++)
        M = fmaxf(M, g_pml[(bs + c) * 128 + row * 2]);

    float L = 0.0f;
    float acc[16];
    #pragma unroll
    for (int e = 0; e < 16; e++) acc[e] = 0.0f;

    for (int c = 0; c < nc; c++) {
        const float mc = g_pml[(bs + c) * 128 + row * 2];
        const float lc = g_pml[(bs + c) * 128 + row * 2 + 1];
        const float w = ex2(mc - M);
        L += w * lc;
        const float* p = g_po + ((size_t)(bs + c) * 64 + row) * 64 + seg;
        #pragma unroll
        for (int e = 0; e < 16; e += 4) {
            float4 v = *(const float4*)(p + e);
            acc[e]     += w * v.x;
            acc[e + 1] += w * v.y;
            acc[e + 2] += w * v.z;
            acc[e + 3] += w * v.w;
        }
    }
    const float inv = 1.0f / L;
    float* q = out + ((size_t)b * T_ + qt * 64 + row) * 64 + seg;
    #pragma unroll
    for (int e = 0; e < 16; e += 4)
        *(float4*)(q + e) = make_float4(acc[e] * inv, acc[e + 1] * inv,
                                        acc[e + 2] * inv, acc[e + 3] * inv);
}

// ---------------------------------------------------------------------------
extern "C" void kernel_launch(void* const* d_in, const int* in_sizes, int n_in,
                              void* d_out, int out_size)
{
    const float* emb = (const float*)d_in[0];
    const float* Wq  = (const float*)d_in[1];
    const float* Wk  = (const float*)d_in[2];
    const float* Wv  = (const float*)d_in[3];
    float* out = (float*)d_out;

    const int psmem = (2 * 128 * PST + 2 * 192 * PST) * (int)sizeof(__nv_bfloat16);
    cudaFuncSetAttribute(proj_kernel, cudaFuncAttributeMaxDynamicSharedMemorySize,
                         psmem);
    proj_kernel<<<128, 256, psmem>>>(emb, Wq, Wk, Wv);

    attn_kernel<<<4 * 288, 128>>>();

    dim3 cg(64, B_, 1);
    combine_kernel<<<cg, 256>>>(out);
}